// round 11
// baseline (speedup 1.0000x reference)
#include <cuda_runtime.h>
#include <cuda_fp16.h>
#include <stdint.h>

// Problem constants
#define MAXN 40000
#define MAXE 640000
#define NG   64
#define F    128
#define SCAN_TILE 1024
#define MAXNB ((MAXN + SCAN_TILE - 1) / SCAN_TILE)   // 40

// ---------------- device scratch (zero at load; each call restores zeros) --
__device__ __half          g_xh[(size_t)MAXN * F];   // fp16 ping
__device__ __half          g_hbuf[(size_t)MAXN * F]; // fp16 pong (prescaled)
__device__ int             g_deg[MAXN];              // MUST be 0 at entry
__device__ float           g_dis[MAXN];
__device__ int             g_rowptr[MAXN + 1];
__device__ int             g_tmp[MAXN];              // scanC overwrites; no invariant
__device__ unsigned short  g_csr[MAXE];              // u16 node ids (N < 65536)
__device__ int             g_blocksums[MAXNB];
__device__ float           g_gsum[NG];               // MUST be 0 at entry
__device__ float           g_gcnt[NG];               // MUST be 0 at entry

// -------- PDL intrinsics --------
__device__ __forceinline__ void gdc_launch() {
    asm volatile("griddepcontrol.launch_dependents;");
}
__device__ __forceinline__ void gdc_wait() {
    asm volatile("griddepcontrol.wait;" ::: "memory");
}

// -------- fused: convert x -> fp16  AND  degree histogram ----------------
__global__ void prep_kernel(const float* __restrict__ x, int total4,
                            const int* __restrict__ col, int E, int n,
                            int cBlocks) {
    gdc_launch();
    if (blockIdx.x < cBlocks) {
        int i = blockIdx.x * blockDim.x + threadIdx.x;
        if (i < total4) {
            float4 v = *(const float4*)(x + (size_t)i * 4);
            __half2 h0 = __floats2half2_rn(v.x, v.y);
            __half2 h1 = __floats2half2_rn(v.z, v.w);
            uint2 pk;
            pk.x = *reinterpret_cast<unsigned*>(&h0);
            pk.y = *reinterpret_cast<unsigned*>(&h1);
            *(uint2*)(g_xh + (size_t)i * 4) = pk;
        }
    } else {
        int i = (blockIdx.x - cBlocks) * blockDim.x + threadIdx.x;
        int e = i * 2;
        if (e + 1 < E) {
            int2 c2 = *(const int2*)(col + e);
            atomicAdd(&g_deg[c2.x], 1);
            atomicAdd(&g_deg[c2.y], 1);
        } else if (e < E) {
            atomicAdd(&g_deg[col[e]], 1);
        }
    }
}

// -------- scan phase A: block sums of (deg+1) + dis = rsqrt(deg+1) --------
__global__ __launch_bounds__(SCAN_TILE)
void scan_phaseA(int n) {
    gdc_launch();
    gdc_wait();
    __shared__ int sh[32];
    int tid = threadIdx.x, lane = tid & 31, wid = tid >> 5;
    int i = blockIdx.x * SCAN_TILE + tid;
    int v = (i < n) ? (g_deg[i] + 1) : 0;   // +1 = self loop (not in CSR)
    if (i < n) g_dis[i] = rsqrtf((float)v);
    int x = v;
#pragma unroll
    for (int o = 16; o > 0; o >>= 1) x += __shfl_xor_sync(0xffffffffu, x, o);
    if (lane == 0) sh[wid] = x;
    __syncthreads();
    if (wid == 0) {
        int w = sh[lane];
#pragma unroll
        for (int o = 16; o > 0; o >>= 1) w += __shfl_xor_sync(0xffffffffu, w, o);
        if (lane == 0) g_blocksums[blockIdx.x] = w;
    }
}

// -------- scan phase C: rowptr over edges only; also seed g_tmp -----------
__global__ __launch_bounds__(SCAN_TILE)
void scan_phaseC(int n, int nb) {
    gdc_launch();
    gdc_wait();
    __shared__ int sh[32];
    __shared__ int bexcl[64];
    __shared__ int w0tot;
    int tid = threadIdx.x, lane = tid & 31, wid = tid >> 5;

    if (tid < 64) {
        int tileN = 0;
        if (tid < nb) {
            int lo = tid * SCAN_TILE;
            int hi = lo + SCAN_TILE; if (hi > n) hi = n;
            tileN = hi - lo;
        }
        int v = (tid < nb) ? (g_blocksums[tid] - tileN) : 0;  // edges only
        int x = v;
#pragma unroll
        for (int o = 1; o < 32; o <<= 1) {
            int y = __shfl_up_sync(0xffffffffu, x, o);
            if (lane >= o) x += y;
        }
        if (tid == 31) w0tot = x;
        bexcl[tid] = x - v;
    }
    __syncthreads();
    if (tid >= 32 && tid < 64) bexcl[tid] += w0tot;
    __syncthreads();
    int blockOff = bexcl[blockIdx.x];
    if (tid == 0 && blockIdx.x == 0) {
        int lastTileN = n - (nb - 1) * SCAN_TILE;
        g_rowptr[n] = bexcl[nb - 1] + g_blocksums[nb - 1] - lastTileN;
    }

    int i = blockIdx.x * SCAN_TILE + tid;
    int v = (i < n) ? g_deg[i] : 0;       // edges only
    int x = v;
#pragma unroll
    for (int o = 1; o < 32; o <<= 1) {
        int y = __shfl_up_sync(0xffffffffu, x, o);
        if (lane >= o) x += y;
    }
    if (lane == 31) sh[wid] = x;
    __syncthreads();
    if (wid == 0) {
        int w = sh[lane];
#pragma unroll
        for (int o = 1; o < 32; o <<= 1) {
            int y = __shfl_up_sync(0xffffffffu, w, o);
            if (lane >= o) w += y;
        }
        sh[lane] = w;
    }
    __syncthreads();
    int woff = (wid > 0) ? sh[wid - 1] : 0;
    if (i < n) {
        int rp = blockOff + woff + x - v;
        g_rowptr[i] = rp;
        g_tmp[i]    = rp;      // scatter's atomic cursor starts at rowptr
    }
}

// -------- scatter edges into u16 CSR, 1 edge per thread -------------------
__global__ void scatter_kernel(const int* __restrict__ row,
                               const int* __restrict__ col, int E) {
    gdc_launch();
    gdc_wait();
    int idx = blockIdx.x * blockDim.x + threadIdx.x;
    if (idx >= E) return;
    int d = __ldg(col + idx);
    int s = __ldg(row + idx);
    int p = atomicAdd(&g_tmp[d], 1);
    g_csr[p] = (unsigned short)s;
}

// ======== Tensor-core GEMM: g_hbuf = half( dis * (g_xh @ W + bias) ) ========
__device__ __forceinline__ void ldsm_x4(uint32_t* r, const __half* p) {
    uint32_t addr = (uint32_t)__cvta_generic_to_shared(p);
    asm volatile("ldmatrix.sync.aligned.m8n8.x4.shared.b16 {%0,%1,%2,%3}, [%4];"
                 : "=r"(r[0]), "=r"(r[1]), "=r"(r[2]), "=r"(r[3]) : "r"(addr));
}
__device__ __forceinline__ void ldsm_x2t(uint32_t* r, const __half* p) {
    uint32_t addr = (uint32_t)__cvta_generic_to_shared(p);
    asm volatile("ldmatrix.sync.aligned.m8n8.x2.trans.shared.b16 {%0,%1}, [%2];"
                 : "=r"(r[0]), "=r"(r[1]) : "r"(addr));
}
__device__ __forceinline__ void mma16816(float* c, const uint32_t* a, const uint32_t* b) {
    asm volatile("mma.sync.aligned.m16n8k16.row.col.f32.f16.f16.f32 "
                 "{%0,%1,%2,%3}, {%4,%5,%6,%7}, {%8,%9}, {%0,%1,%2,%3};"
                 : "+f"(c[0]), "+f"(c[1]), "+f"(c[2]), "+f"(c[3])
                 : "r"(a[0]), "r"(a[1]), "r"(a[2]), "r"(a[3]), "r"(b[0]), "r"(b[1]));
}

#define LDA 72   // 64 + 8 halves pad
#define LDB 136  // 128 + 8 halves pad

__global__ __launch_bounds__(256)
void gemm_tc_kernel(const float* __restrict__ W,
                    const float* __restrict__ bias, int M) {
    __shared__ __half sA[128 * LDA];
    __shared__ __half sB[64 * LDB];
    __shared__ float sBias[128];

    gdc_launch();
    const int t = threadIdx.x;
    const int wid = t >> 5, lane = t & 31;
    const int blockM = blockIdx.x * 128;
    const int warpM = (wid >> 1) * 32;
    const int warpN = (wid & 1) * 64;

    if (t < 128) sBias[t] = bias[t];   // external input: safe pre-wait

    float c[2][8][4];
#pragma unroll
    for (int mi = 0; mi < 2; mi++)
#pragma unroll
        for (int ni = 0; ni < 8; ni++)
#pragma unroll
            for (int q = 0; q < 4; q++) c[mi][ni][q] = 0.f;

    gdc_wait();   // before reading g_xh / g_dis

#pragma unroll
    for (int stage = 0; stage < 2; stage++) {
        const int kOff = stage * 64;
#pragma unroll
        for (int l = 0; l < 4; l++) {
            int idx = (t + l * 256) * 8;
            int row = idx >> 6;
            int col = idx & 63;
            int grow = blockM + row;
            uint4 v = make_uint4(0u, 0u, 0u, 0u);
            if (grow < M)
                v = *(const uint4*)(g_xh + (size_t)grow * 128 + kOff + col);
            *(uint4*)(sA + row * LDA + col) = v;
        }
#pragma unroll
        for (int l = 0; l < 8; l++) {
            int idx = (t + l * 256) * 4;
            int row = idx >> 7;
            int col = idx & 127;
            float4 v = *(const float4*)(W + (size_t)(kOff + row) * 128 + col);
            __half2 h0 = __floats2half2_rn(v.x, v.y);
            __half2 h1 = __floats2half2_rn(v.z, v.w);
            uint2 pk;
            pk.x = *reinterpret_cast<unsigned*>(&h0);
            pk.y = *reinterpret_cast<unsigned*>(&h1);
            *(uint2*)(sB + row * LDB + col) = pk;
        }
        __syncthreads();

#pragma unroll
        for (int ks = 0; ks < 4; ks++) {
            const int kb = ks * 16;
            uint32_t a[2][4];
#pragma unroll
            for (int mi = 0; mi < 2; mi++) {
                int r = warpM + mi * 16 + (lane & 15);
                int cc = kb + ((lane >> 4) << 3);
                ldsm_x4(a[mi], sA + r * LDA + cc);
            }
#pragma unroll
            for (int ni = 0; ni < 8; ni++) {
                uint32_t b[2];
                int r = kb + (lane & 15);
                int cc = warpN + ni * 8;
                ldsm_x2t(b, sB + r * LDB + cc);
                mma16816(c[0][ni], a[0], b);
                mma16816(c[1][ni], a[1], b);
            }
        }
        __syncthreads();
    }

#pragma unroll
    for (int mi = 0; mi < 2; mi++) {
        int rBase = blockM + warpM + mi * 16 + (lane >> 2);
#pragma unroll
        for (int hh = 0; hh < 2; hh++) {
            int r = rBase + hh * 8;
            if (r < M) {
                float ds = g_dis[r];
#pragma unroll
                for (int ni = 0; ni < 8; ni++) {
                    int col = warpN + ni * 8 + (lane & 3) * 2;
                    float v0 = (c[mi][ni][hh * 2 + 0] + sBias[col]) * ds;
                    float v1 = (c[mi][ni][hh * 2 + 1] + sBias[col + 1]) * ds;
                    __half2 hv = __floats2half2_rn(v0, v1);
                    *(__half2*)(g_hbuf + (size_t)r * 128 + col) = hv;
                }
            }
        }
    }
}

// ======== CSR gather aggregation (fp16 rows, fp32 accumulate) ========
__device__ __forceinline__ void accum_row(float acc[4], const __half* rowp, int lane) {
    uint2 u = *(const uint2*)(rowp + lane * 4);
    __half2 h0 = *reinterpret_cast<__half2*>(&u.x);
    __half2 h1 = *reinterpret_cast<__half2*>(&u.y);
    float2 f0 = __half22float2(h0);
    float2 f1 = __half22float2(h1);
    acc[0] += f0.x; acc[1] += f0.y; acc[2] += f1.x; acc[3] += f1.y;
}

template <bool POOL>
__global__ __launch_bounds__(512)
void aggregate_kernel(int n, const int* __restrict__ batch,
                      const float* __restrict__ Wl) {
    gdc_launch();
    gdc_wait();
    int node = blockIdx.x * 16 + (threadIdx.x >> 5);
    if (node >= n) return;
    int lane = threadIdx.x & 31;
    const __half* __restrict__ h = g_hbuf;
    int s = g_rowptr[node];
    int e = g_rowptr[node + 1];
    float acc[4] = {0.f, 0.f, 0.f, 0.f};

    accum_row(acc, h + (size_t)node * 128, lane);   // self loop

    int p = s;
    for (; p + 4 <= e; p += 4) {
        int si[4];
#pragma unroll
        for (int q = 0; q < 4; q++) si[q] = (int)g_csr[p + q];
#pragma unroll
        for (int q = 0; q < 4; q++)
            accum_row(acc, h + (size_t)si[q] * 128, lane);
    }
    for (; p < e; p++)
        accum_row(acc, h + (size_t)(int)g_csr[p] * 128, lane);

    float dd = g_dis[node];
#pragma unroll
    for (int j = 0; j < 4; j++) acc[j] = fmaxf(acc[j] * dd, 0.f);

    if (POOL) {
        float4 w = *(const float4*)(Wl + lane * 4);
        float sv = acc[0] * w.x + acc[1] * w.y + acc[2] * w.z + acc[3] * w.w;
#pragma unroll
        for (int o = 16; o > 0; o >>= 1) sv += __shfl_xor_sync(0xffffffffu, sv, o);
        if (lane == 0) {
            unsigned b = (unsigned)batch[node];
            if (b < NG) {
                atomicAdd(&g_gsum[b], sv);
                atomicAdd(&g_gcnt[b], 1.0f);
            }
        }
    } else {
        __half2 o0 = __floats2half2_rn(acc[0], acc[1]);
        __half2 o1 = __floats2half2_rn(acc[2], acc[3]);
        uint2 pk;
        pk.x = *reinterpret_cast<unsigned*>(&o0);
        pk.y = *reinterpret_cast<unsigned*>(&o1);
        *(uint2*)(g_xh + (size_t)node * 128 + lane * 4) = pk;
        // restore zero-state for next call (runs layers 1,2; idempotent)
        if (lane == 0) g_deg[node] = 0;
    }
}

__global__ void final_kernel(float* __restrict__ out, const float* __restrict__ bl) {
    gdc_wait();
    int g = threadIdx.x;
    if (g < NG) {
        out[g] = g_gsum[g] / fmaxf(g_gcnt[g], 1.0f) + bl[0];
        g_gsum[g] = 0.f;
        g_gcnt[g] = 0.f;
    }
}

// --------------------------------------------------------------------------
template <typename... Args>
static void launch_pdl(void (*kern)(Args...), dim3 grid, dim3 block,
                       Args... args) {
    cudaLaunchConfig_t cfg = {};
    cfg.gridDim = grid;
    cfg.blockDim = block;
    cudaLaunchAttribute attr[1];
    attr[0].id = cudaLaunchAttributeProgrammaticStreamSerialization;
    attr[0].val.programmaticStreamSerializationAllowed = 1;
    cfg.attrs = attr;
    cfg.numAttrs = 1;
    cudaLaunchKernelEx(&cfg, kern, args...);
}

extern "C" void kernel_launch(void* const* d_in, const int* in_sizes, int n_in,
                              void* d_out, int out_size) {
    const float* x     = (const float*)d_in[0];
    const int*   eidx  = (const int*)d_in[1];
    const int*   batch = (const int*)d_in[2];

    int wbase = (in_sizes[3] < 128) ? 4 : 3;
    const float* W1 = (const float*)d_in[wbase + 0];
    const float* b1 = (const float*)d_in[wbase + 1];
    const float* W2 = (const float*)d_in[wbase + 2];
    const float* b2 = (const float*)d_in[wbase + 3];
    const float* W3 = (const float*)d_in[wbase + 4];
    const float* b3 = (const float*)d_in[wbase + 5];
    const float* Wl = (const float*)d_in[wbase + 6];
    const float* bl = (const float*)d_in[wbase + 7];
    float* out = (float*)d_out;

    const int N = in_sizes[0] / F;          // 40000
    const int E = in_sizes[1] / 2;          // 640000
    const int* erow = eidx;
    const int* ecol = eidx + E;
    const int NB = (N + SCAN_TILE - 1) / SCAN_TILE;

    const int T = 256;
    const int total4  = N * F / 4;
    const int cBlocks = (total4 + T - 1) / T;
    const int eBlocks2 = ((E + 1) / 2 + T - 1) / T;   // prep counting (2/thread)
    const int eBlocks1 = (E + T - 1) / T;             // scatter (1/thread)

    prep_kernel<<<cBlocks + eBlocks2, T>>>(x, total4, ecol, E, N, cBlocks);

    launch_pdl(scan_phaseA, dim3(NB), dim3(SCAN_TILE), N);
    launch_pdl(scan_phaseC, dim3(NB), dim3(SCAN_TILE), N, NB);
    launch_pdl(scatter_kernel, dim3(eBlocks1), dim3(T), erow, ecol, E);

    const int gemmBlocks = (N + 127) / 128;
    const int aggBlocks  = (N + 15) / 16;

    launch_pdl(gemm_tc_kernel, dim3(gemmBlocks), dim3(256), W1, b1, N);
    launch_pdl(aggregate_kernel<false>, dim3(aggBlocks), dim3(512), N, batch, Wl);
    launch_pdl(gemm_tc_kernel, dim3(gemmBlocks), dim3(256), W2, b2, N);
    launch_pdl(aggregate_kernel<false>, dim3(aggBlocks), dim3(512), N, batch, Wl);
    launch_pdl(gemm_tc_kernel, dim3(gemmBlocks), dim3(256), W3, b3, N);
    launch_pdl(aggregate_kernel<true>, dim3(aggBlocks), dim3(512), N, batch, Wl);

    launch_pdl(final_kernel, dim3(1), dim3(64), out, (const float*)bl);
}

// round 12
// speedup vs baseline: 1.0058x; 1.0058x over previous
#include <cuda_runtime.h>
#include <cuda_fp16.h>
#include <stdint.h>

// Problem constants
#define MAXN 40000
#define MAXE 640000
#define NG   64
#define F    128
#define SCAN_TILE 1024
#define MAXNB ((MAXN + SCAN_TILE - 1) / SCAN_TILE)   // 40

// ---------------- device scratch (zero at load; each call restores zeros) --
__device__ __half          g_xh[(size_t)MAXN * F];   // fp16 ping
__device__ __half          g_hbuf[(size_t)MAXN * F]; // fp16 pong (prescaled)
__device__ int             g_deg[MAXN];              // MUST be 0 at entry
__device__ float           g_dis[MAXN];
__device__ int             g_rowptr[MAXN + 1];
__device__ int             g_tmp[MAXN];              // scanC overwrites each call
__device__ unsigned short  g_csr[MAXE];              // u16 node ids (N < 65536)
__device__ int             g_blocksums[MAXNB];
__device__ float           g_gsum[NG];               // MUST be 0 at entry
__device__ float           g_gcnt[NG];               // MUST be 0 at entry

// -------- PDL intrinsics --------
__device__ __forceinline__ void gdc_launch() {
    asm volatile("griddepcontrol.launch_dependents;");
}
__device__ __forceinline__ void gdc_wait() {
    asm volatile("griddepcontrol.wait;" ::: "memory");
}

// -------- fused: convert x -> fp16  AND  degree histogram (REDG) ---------
__global__ void prep_kernel(const float* __restrict__ x, int total4,
                            const int* __restrict__ col, int E, int n,
                            int cBlocks) {
    gdc_launch();
    if (blockIdx.x < cBlocks) {
        int i = blockIdx.x * blockDim.x + threadIdx.x;
        if (i < total4) {
            float4 v = *(const float4*)(x + (size_t)i * 4);
            __half2 h0 = __floats2half2_rn(v.x, v.y);
            __half2 h1 = __floats2half2_rn(v.z, v.w);
            uint2 pk;
            pk.x = *reinterpret_cast<unsigned*>(&h0);
            pk.y = *reinterpret_cast<unsigned*>(&h1);
            *(uint2*)(g_xh + (size_t)i * 4) = pk;
        }
    } else {
        int i = (blockIdx.x - cBlocks) * blockDim.x + threadIdx.x;
        int e = i * 4;
        if (e + 4 <= E) {
            int4 c4 = *(const int4*)(col + e);
            atomicAdd(&g_deg[c4.x], 1);   // result unused -> REDG, no stall
            atomicAdd(&g_deg[c4.y], 1);
            atomicAdd(&g_deg[c4.z], 1);
            atomicAdd(&g_deg[c4.w], 1);
        } else {
            for (int q = e; q < E; q++) atomicAdd(&g_deg[col[q]], 1);
        }
    }
}

// -------- scan phase A: block sums of (deg+1) + dis = rsqrt(deg+1) --------
__global__ __launch_bounds__(SCAN_TILE)
void scan_phaseA(int n) {
    gdc_launch();
    gdc_wait();
    __shared__ int sh[32];
    int tid = threadIdx.x, lane = tid & 31, wid = tid >> 5;
    int i = blockIdx.x * SCAN_TILE + tid;
    int v = (i < n) ? (g_deg[i] + 1) : 0;   // +1 = self loop (not in CSR)
    if (i < n) g_dis[i] = rsqrtf((float)v);
    int x = v;
#pragma unroll
    for (int o = 16; o > 0; o >>= 1) x += __shfl_xor_sync(0xffffffffu, x, o);
    if (lane == 0) sh[wid] = x;
    __syncthreads();
    if (wid == 0) {
        int w = sh[lane];
#pragma unroll
        for (int o = 16; o > 0; o >>= 1) w += __shfl_xor_sync(0xffffffffu, w, o);
        if (lane == 0) g_blocksums[blockIdx.x] = w;
    }
}

// -------- scan phase C: rowptr over edges only; also seed g_tmp -----------
__global__ __launch_bounds__(SCAN_TILE)
void scan_phaseC(int n, int nb) {
    gdc_launch();
    gdc_wait();
    __shared__ int sh[32];
    __shared__ int bexcl[64];
    __shared__ int w0tot;
    int tid = threadIdx.x, lane = tid & 31, wid = tid >> 5;

    if (tid < 64) {
        int tileN = 0;
        if (tid < nb) {
            int lo = tid * SCAN_TILE;
            int hi = lo + SCAN_TILE; if (hi > n) hi = n;
            tileN = hi - lo;
        }
        int v = (tid < nb) ? (g_blocksums[tid] - tileN) : 0;  // edges only
        int x = v;
#pragma unroll
        for (int o = 1; o < 32; o <<= 1) {
            int y = __shfl_up_sync(0xffffffffu, x, o);
            if (lane >= o) x += y;
        }
        if (tid == 31) w0tot = x;
        bexcl[tid] = x - v;
    }
    __syncthreads();
    if (tid >= 32 && tid < 64) bexcl[tid] += w0tot;
    __syncthreads();
    int blockOff = bexcl[blockIdx.x];
    if (tid == 0 && blockIdx.x == 0) {
        int lastTileN = n - (nb - 1) * SCAN_TILE;
        g_rowptr[n] = bexcl[nb - 1] + g_blocksums[nb - 1] - lastTileN;
    }

    int i = blockIdx.x * SCAN_TILE + tid;
    int v = (i < n) ? g_deg[i] : 0;       // edges only
    int x = v;
#pragma unroll
    for (int o = 1; o < 32; o <<= 1) {
        int y = __shfl_up_sync(0xffffffffu, x, o);
        if (lane >= o) x += y;
    }
    if (lane == 31) sh[wid] = x;
    __syncthreads();
    if (wid == 0) {
        int w = sh[lane];
#pragma unroll
        for (int o = 1; o < 32; o <<= 1) {
            int y = __shfl_up_sync(0xffffffffu, w, o);
            if (lane >= o) w += y;
        }
        sh[lane] = w;
    }
    __syncthreads();
    int woff = (wid > 0) ? sh[wid - 1] : 0;
    if (i < n) {
        int rp = blockOff + woff + x - v;
        g_rowptr[i] = rp;
        g_tmp[i]    = rp;      // scatter's atomic cursor starts at rowptr
    }
}

// -------- scatter: 4 edges/thread, batched independent atomics ------------
__global__ void scatter_kernel(const int* __restrict__ row,
                               const int* __restrict__ col, int E) {
    gdc_launch();
    gdc_wait();
    int base = (blockIdx.x * blockDim.x + threadIdx.x) * 4;
    if (base + 4 <= E) {
        int4 d4 = *(const int4*)(col + base);
        int4 s4 = *(const int4*)(row + base);
        int p0 = atomicAdd(&g_tmp[d4.x], 1);   // 4 independent ATOMGs in flight
        int p1 = atomicAdd(&g_tmp[d4.y], 1);
        int p2 = atomicAdd(&g_tmp[d4.z], 1);
        int p3 = atomicAdd(&g_tmp[d4.w], 1);
        g_csr[p0] = (unsigned short)s4.x;
        g_csr[p1] = (unsigned short)s4.y;
        g_csr[p2] = (unsigned short)s4.z;
        g_csr[p3] = (unsigned short)s4.w;
    } else if (base < E) {
        for (int idx = base; idx < E; idx++) {
            int p = atomicAdd(&g_tmp[col[idx]], 1);
            g_csr[p] = (unsigned short)row[idx];
        }
    }
}

// ======== Tensor-core GEMM: g_hbuf = half( dis * (g_xh @ W + bias) ) ========
__device__ __forceinline__ void ldsm_x4(uint32_t* r, const __half* p) {
    uint32_t addr = (uint32_t)__cvta_generic_to_shared(p);
    asm volatile("ldmatrix.sync.aligned.m8n8.x4.shared.b16 {%0,%1,%2,%3}, [%4];"
                 : "=r"(r[0]), "=r"(r[1]), "=r"(r[2]), "=r"(r[3]) : "r"(addr));
}
__device__ __forceinline__ void ldsm_x2t(uint32_t* r, const __half* p) {
    uint32_t addr = (uint32_t)__cvta_generic_to_shared(p);
    asm volatile("ldmatrix.sync.aligned.m8n8.x2.trans.shared.b16 {%0,%1}, [%2];"
                 : "=r"(r[0]), "=r"(r[1]) : "r"(addr));
}
__device__ __forceinline__ void mma16816(float* c, const uint32_t* a, const uint32_t* b) {
    asm volatile("mma.sync.aligned.m16n8k16.row.col.f32.f16.f16.f32 "
                 "{%0,%1,%2,%3}, {%4,%5,%6,%7}, {%8,%9}, {%0,%1,%2,%3};"
                 : "+f"(c[0]), "+f"(c[1]), "+f"(c[2]), "+f"(c[3])
                 : "r"(a[0]), "r"(a[1]), "r"(a[2]), "r"(a[3]), "r"(b[0]), "r"(b[1]));
}

#define LDA 72   // 64 + 8 halves pad
#define LDB 136  // 128 + 8 halves pad

__global__ __launch_bounds__(256)
void gemm_tc_kernel(const float* __restrict__ W,
                    const float* __restrict__ bias, int M) {
    __shared__ __half sA[128 * LDA];
    __shared__ __half sB[2][64 * LDB];    // both K-stages of W
    __shared__ float sBias[128];

    gdc_launch();
    const int t = threadIdx.x;
    const int wid = t >> 5, lane = t & 31;
    const int blockM = blockIdx.x * 128;
    const int warpM = (wid >> 1) * 32;
    const int warpN = (wid & 1) * 64;

    // ---- PDL pre-wait work: stage ALL of W + bias (external inputs) ----
    if (t < 128) sBias[t] = bias[t];
#pragma unroll
    for (int stage = 0; stage < 2; stage++) {
        const int kOff = stage * 64;
#pragma unroll
        for (int l = 0; l < 8; l++) {
            int idx = (t + l * 256) * 4;
            int row = idx >> 7;
            int col = idx & 127;
            float4 v = *(const float4*)(W + (size_t)(kOff + row) * 128 + col);
            __half2 h0 = __floats2half2_rn(v.x, v.y);
            __half2 h1 = __floats2half2_rn(v.z, v.w);
            uint2 pk;
            pk.x = *reinterpret_cast<unsigned*>(&h0);
            pk.y = *reinterpret_cast<unsigned*>(&h1);
            *(uint2*)(sB[stage] + row * LDB + col) = pk;
        }
    }

    float c[2][8][4];
#pragma unroll
    for (int mi = 0; mi < 2; mi++)
#pragma unroll
        for (int ni = 0; ni < 8; ni++)
#pragma unroll
            for (int q = 0; q < 4; q++) c[mi][ni][q] = 0.f;

    gdc_wait();   // now wait for g_xh / g_dis producers

#pragma unroll
    for (int stage = 0; stage < 2; stage++) {
        const int kOff = stage * 64;
#pragma unroll
        for (int l = 0; l < 4; l++) {
            int idx = (t + l * 256) * 8;
            int row = idx >> 6;
            int col = idx & 63;
            int grow = blockM + row;
            uint4 v = make_uint4(0u, 0u, 0u, 0u);
            if (grow < M)
                v = *(const uint4*)(g_xh + (size_t)grow * 128 + kOff + col);
            *(uint4*)(sA + row * LDA + col) = v;
        }
        __syncthreads();

#pragma unroll
        for (int ks = 0; ks < 4; ks++) {
            const int kb = ks * 16;
            uint32_t a[2][4];
#pragma unroll
            for (int mi = 0; mi < 2; mi++) {
                int r = warpM + mi * 16 + (lane & 15);
                int cc = kb + ((lane >> 4) << 3);
                ldsm_x4(a[mi], sA + r * LDA + cc);
            }
#pragma unroll
            for (int ni = 0; ni < 8; ni++) {
                uint32_t b[2];
                int r = kb + (lane & 15);
                int cc = warpN + ni * 8;
                ldsm_x2t(b, sB[stage] + r * LDB + cc);
                mma16816(c[0][ni], a[0], b);
                mma16816(c[1][ni], a[1], b);
            }
        }
        __syncthreads();
    }

#pragma unroll
    for (int mi = 0; mi < 2; mi++) {
        int rBase = blockM + warpM + mi * 16 + (lane >> 2);
#pragma unroll
        for (int hh = 0; hh < 2; hh++) {
            int r = rBase + hh * 8;
            if (r < M) {
                float ds = g_dis[r];
#pragma unroll
                for (int ni = 0; ni < 8; ni++) {
                    int col = warpN + ni * 8 + (lane & 3) * 2;
                    float v0 = (c[mi][ni][hh * 2 + 0] + sBias[col]) * ds;
                    float v1 = (c[mi][ni][hh * 2 + 1] + sBias[col + 1]) * ds;
                    __half2 hv = __floats2half2_rn(v0, v1);
                    *(__half2*)(g_hbuf + (size_t)r * 128 + col) = hv;
                }
            }
        }
    }
}

// ======== CSR gather aggregation (fp16 rows, fp32 accumulate) ========
__device__ __forceinline__ void accum_row(float acc[4], const __half* rowp, int lane) {
    uint2 u = *(const uint2*)(rowp + lane * 4);
    __half2 h0 = *reinterpret_cast<__half2*>(&u.x);
    __half2 h1 = *reinterpret_cast<__half2*>(&u.y);
    float2 f0 = __half22float2(h0);
    float2 f1 = __half22float2(h1);
    acc[0] += f0.x; acc[1] += f0.y; acc[2] += f1.x; acc[3] += f1.y;
}

template <bool POOL>
__global__ __launch_bounds__(512)
void aggregate_kernel(int n, const int* __restrict__ batch,
                      const float* __restrict__ Wl) {
    gdc_launch();
    int node = blockIdx.x * 16 + (threadIdx.x >> 5);
    int lane = threadIdx.x & 31;
    // PDL pre-wait: CSR topology is stable once scatter finished, which is
    // transitively guaranteed by the preceding gemm's completion.
    int s = 0, e = 0;
    if (node < n) { s = g_rowptr[node]; e = g_rowptr[node + 1]; }
    gdc_wait();
    if (node >= n) return;
    const __half* __restrict__ h = g_hbuf;
    float acc[4] = {0.f, 0.f, 0.f, 0.f};

    accum_row(acc, h + (size_t)node * 128, lane);   // self loop

    int p = s;
    for (; p + 4 <= e; p += 4) {
        int si[4];
#pragma unroll
        for (int q = 0; q < 4; q++) si[q] = (int)g_csr[p + q];
#pragma unroll
        for (int q = 0; q < 4; q++)
            accum_row(acc, h + (size_t)si[q] * 128, lane);
    }
    for (; p < e; p++)
        accum_row(acc, h + (size_t)(int)g_csr[p] * 128, lane);

    float dd = g_dis[node];
#pragma unroll
    for (int j = 0; j < 4; j++) acc[j] = fmaxf(acc[j] * dd, 0.f);

    if (POOL) {
        float4 w = *(const float4*)(Wl + lane * 4);
        float sv = acc[0] * w.x + acc[1] * w.y + acc[2] * w.z + acc[3] * w.w;
#pragma unroll
        for (int o = 16; o > 0; o >>= 1) sv += __shfl_xor_sync(0xffffffffu, sv, o);
        if (lane == 0) {
            unsigned b = (unsigned)batch[node];
            if (b < NG) {
                atomicAdd(&g_gsum[b], sv);
                atomicAdd(&g_gcnt[b], 1.0f);
            }
        }
    } else {
        __half2 o0 = __floats2half2_rn(acc[0], acc[1]);
        __half2 o1 = __floats2half2_rn(acc[2], acc[3]);
        uint2 pk;
        pk.x = *reinterpret_cast<unsigned*>(&o0);
        pk.y = *reinterpret_cast<unsigned*>(&o1);
        *(uint2*)(g_xh + (size_t)node * 128 + lane * 4) = pk;
        // restore zero-state for next call (runs layers 1,2; idempotent)
        if (lane == 0) g_deg[node] = 0;
    }
}

__global__ void final_kernel(float* __restrict__ out, const float* __restrict__ bl) {
    gdc_wait();
    int g = threadIdx.x;
    if (g < NG) {
        out[g] = g_gsum[g] / fmaxf(g_gcnt[g], 1.0f) + bl[0];
        g_gsum[g] = 0.f;
        g_gcnt[g] = 0.f;
    }
}

// --------------------------------------------------------------------------
template <typename... Args>
static void launch_pdl(void (*kern)(Args...), dim3 grid, dim3 block,
                       Args... args) {
    cudaLaunchConfig_t cfg = {};
    cfg.gridDim = grid;
    cfg.blockDim = block;
    cudaLaunchAttribute attr[1];
    attr[0].id = cudaLaunchAttributeProgrammaticStreamSerialization;
    attr[0].val.programmaticStreamSerializationAllowed = 1;
    cfg.attrs = attr;
    cfg.numAttrs = 1;
    cudaLaunchKernelEx(&cfg, kern, args...);
}

extern "C" void kernel_launch(void* const* d_in, const int* in_sizes, int n_in,
                              void* d_out, int out_size) {
    const float* x     = (const float*)d_in[0];
    const int*   eidx  = (const int*)d_in[1];
    const int*   batch = (const int*)d_in[2];

    int wbase = (in_sizes[3] < 128) ? 4 : 3;
    const float* W1 = (const float*)d_in[wbase + 0];
    const float* b1 = (const float*)d_in[wbase + 1];
    const float* W2 = (const float*)d_in[wbase + 2];
    const float* b2 = (const float*)d_in[wbase + 3];
    const float* W3 = (const float*)d_in[wbase + 4];
    const float* b3 = (const float*)d_in[wbase + 5];
    const float* Wl = (const float*)d_in[wbase + 6];
    const float* bl = (const float*)d_in[wbase + 7];
    float* out = (float*)d_out;

    const int N = in_sizes[0] / F;          // 40000
    const int E = in_sizes[1] / 2;          // 640000
    const int* erow = eidx;
    const int* ecol = eidx + E;
    const int NB = (N + SCAN_TILE - 1) / SCAN_TILE;

    const int T = 256;
    const int total4  = N * F / 4;
    const int cBlocks = (total4 + T - 1) / T;
    const int eBlocks4 = ((E + 3) / 4 + T - 1) / T;   // 4 edges/thread

    prep_kernel<<<cBlocks + eBlocks4, T>>>(x, total4, ecol, E, N, cBlocks);

    launch_pdl(scan_phaseA, dim3(NB), dim3(SCAN_TILE), N);
    launch_pdl(scan_phaseC, dim3(NB), dim3(SCAN_TILE), N, NB);
    launch_pdl(scatter_kernel, dim3(eBlocks4), dim3(T), erow, ecol, E);

    const int gemmBlocks = (N + 127) / 128;
    const int aggBlocks  = (N + 15) / 16;

    launch_pdl(gemm_tc_kernel, dim3(gemmBlocks), dim3(256), W1, b1, N);
    launch_pdl(aggregate_kernel<false>, dim3(aggBlocks), dim3(512), N, batch, Wl);
    launch_pdl(gemm_tc_kernel, dim3(gemmBlocks), dim3(256), W2, b2, N);
    launch_pdl(aggregate_kernel<false>, dim3(aggBlocks), dim3(512), N, batch, Wl);
    launch_pdl(gemm_tc_kernel, dim3(gemmBlocks), dim3(256), W3, b3, N);
    launch_pdl(aggregate_kernel<true>, dim3(aggBlocks), dim3(512), N, batch, Wl);

    launch_pdl(final_kernel, dim3(1), dim3(64), out, (const float*)bl);
}

// round 13
// speedup vs baseline: 1.0822x; 1.0760x over previous
#include <cuda_runtime.h>
#include <cuda_fp16.h>
#include <stdint.h>

// Problem constants
#define MAXN 40000
#define MAXE 640000
#define NG   64
#define F    128
#define SCAN_TILE 1024
#define MAXNB ((MAXN + SCAN_TILE - 1) / SCAN_TILE)   // 40

// ---------------- device scratch (zero at load; each call restores zeros) --
__device__ __half          g_xh[(size_t)MAXN * F];   // fp16 ping
__device__ __half          g_hbuf[(size_t)MAXN * F]; // fp16 pong (prescaled)
__device__ int             g_deg[MAXN];              // MUST be 0 at entry
__device__ float           g_dis[MAXN];
__device__ int             g_rowptr[MAXN + 1];
__device__ int             g_tmp[MAXN];              // scanC overwrites each call
__device__ unsigned short  g_csr[MAXE];              // u16 node ids (N < 65536)
__device__ int             g_blocksums[MAXNB];
__device__ float           g_gsum[NG];               // MUST be 0 at entry
__device__ float           g_gcnt[NG];               // MUST be 0 at entry

// -------- PDL intrinsics --------
__device__ __forceinline__ void gdc_launch() {
    asm volatile("griddepcontrol.launch_dependents;");
}
__device__ __forceinline__ void gdc_wait() {
    asm volatile("griddepcontrol.wait;" ::: "memory");
}

// -------- fused: convert x -> fp16  AND  degree histogram (REDG) ---------
__global__ void prep_kernel(const float* __restrict__ x, int total4,
                            const int* __restrict__ col, int E, int n,
                            int cBlocks) {
    gdc_launch();
    if (blockIdx.x < cBlocks) {
        int i = blockIdx.x * blockDim.x + threadIdx.x;
        if (i < total4) {
            float4 v = *(const float4*)(x + (size_t)i * 4);
            __half2 h0 = __floats2half2_rn(v.x, v.y);
            __half2 h1 = __floats2half2_rn(v.z, v.w);
            uint2 pk;
            pk.x = *reinterpret_cast<unsigned*>(&h0);
            pk.y = *reinterpret_cast<unsigned*>(&h1);
            *(uint2*)(g_xh + (size_t)i * 4) = pk;
        }
    } else {
        int i = (blockIdx.x - cBlocks) * blockDim.x + threadIdx.x;
        int e = i * 4;
        if (e + 4 <= E) {
            int4 c4 = *(const int4*)(col + e);
            atomicAdd(&g_deg[c4.x], 1);   // result unused -> REDG
            atomicAdd(&g_deg[c4.y], 1);
            atomicAdd(&g_deg[c4.z], 1);
            atomicAdd(&g_deg[c4.w], 1);
        } else {
            for (int q = e; q < E; q++) atomicAdd(&g_deg[col[q]], 1);
        }
    }
}

// -------- scan phase A: block sums of (deg+1) + dis = rsqrt(deg+1) --------
__global__ __launch_bounds__(SCAN_TILE)
void scan_phaseA(int n) {
    gdc_launch();
    gdc_wait();
    __shared__ int sh[32];
    int tid = threadIdx.x, lane = tid & 31, wid = tid >> 5;
    int i = blockIdx.x * SCAN_TILE + tid;
    int v = (i < n) ? (g_deg[i] + 1) : 0;   // +1 = self loop (not in CSR)
    if (i < n) g_dis[i] = rsqrtf((float)v);
    int x = v;
#pragma unroll
    for (int o = 16; o > 0; o >>= 1) x += __shfl_xor_sync(0xffffffffu, x, o);
    if (lane == 0) sh[wid] = x;
    __syncthreads();
    if (wid == 0) {
        int w = sh[lane];
#pragma unroll
        for (int o = 16; o > 0; o >>= 1) w += __shfl_xor_sync(0xffffffffu, w, o);
        if (lane == 0) g_blocksums[blockIdx.x] = w;
    }
}

// -------- scan phase C: rowptr over edges only; also seed g_tmp -----------
__global__ __launch_bounds__(SCAN_TILE)
void scan_phaseC(int n, int nb) {
    gdc_launch();
    gdc_wait();
    __shared__ int sh[32];
    __shared__ int bexcl[64];
    __shared__ int w0tot;
    int tid = threadIdx.x, lane = tid & 31, wid = tid >> 5;

    if (tid < 64) {
        int tileN = 0;
        if (tid < nb) {
            int lo = tid * SCAN_TILE;
            int hi = lo + SCAN_TILE; if (hi > n) hi = n;
            tileN = hi - lo;
        }
        int v = (tid < nb) ? (g_blocksums[tid] - tileN) : 0;  // edges only
        int x = v;
#pragma unroll
        for (int o = 1; o < 32; o <<= 1) {
            int y = __shfl_up_sync(0xffffffffu, x, o);
            if (lane >= o) x += y;
        }
        if (tid == 31) w0tot = x;
        bexcl[tid] = x - v;
    }
    __syncthreads();
    if (tid >= 32 && tid < 64) bexcl[tid] += w0tot;
    __syncthreads();
    int blockOff = bexcl[blockIdx.x];
    if (tid == 0 && blockIdx.x == 0) {
        int lastTileN = n - (nb - 1) * SCAN_TILE;
        g_rowptr[n] = bexcl[nb - 1] + g_blocksums[nb - 1] - lastTileN;
    }

    int i = blockIdx.x * SCAN_TILE + tid;
    int v = (i < n) ? g_deg[i] : 0;       // edges only
    int x = v;
#pragma unroll
    for (int o = 1; o < 32; o <<= 1) {
        int y = __shfl_up_sync(0xffffffffu, x, o);
        if (lane >= o) x += y;
    }
    if (lane == 31) sh[wid] = x;
    __syncthreads();
    if (wid == 0) {
        int w = sh[lane];
#pragma unroll
        for (int o = 1; o < 32; o <<= 1) {
            int y = __shfl_up_sync(0xffffffffu, w, o);
            if (lane >= o) w += y;
        }
        sh[lane] = w;
    }
    __syncthreads();
    int woff = (wid > 0) ? sh[wid - 1] : 0;
    if (i < n) {
        int rp = blockOff + woff + x - v;
        g_rowptr[i] = rp;
        g_tmp[i]    = rp;      // scatter's atomic cursor starts at rowptr
    }
}

// ======== Tensor-core GEMM (optionally fused with CSR scatter) ========
// FUSE: blocks [0, nGemmBlocks) do the GEMM; blocks beyond do the edge
// scatter (independent work — overlaps GEMM compute with ATOMG latency).
__device__ __forceinline__ void ldsm_x4(uint32_t* r, const __half* p) {
    uint32_t addr = (uint32_t)__cvta_generic_to_shared(p);
    asm volatile("ldmatrix.sync.aligned.m8n8.x4.shared.b16 {%0,%1,%2,%3}, [%4];"
                 : "=r"(r[0]), "=r"(r[1]), "=r"(r[2]), "=r"(r[3]) : "r"(addr));
}
__device__ __forceinline__ void ldsm_x2t(uint32_t* r, const __half* p) {
    uint32_t addr = (uint32_t)__cvta_generic_to_shared(p);
    asm volatile("ldmatrix.sync.aligned.m8n8.x2.trans.shared.b16 {%0,%1}, [%2];"
                 : "=r"(r[0]), "=r"(r[1]) : "r"(addr));
}
__device__ __forceinline__ void mma16816(float* c, const uint32_t* a, const uint32_t* b) {
    asm volatile("mma.sync.aligned.m16n8k16.row.col.f32.f16.f16.f32 "
                 "{%0,%1,%2,%3}, {%4,%5,%6,%7}, {%8,%9}, {%0,%1,%2,%3};"
                 : "+f"(c[0]), "+f"(c[1]), "+f"(c[2]), "+f"(c[3])
                 : "r"(a[0]), "r"(a[1]), "r"(a[2]), "r"(a[3]), "r"(b[0]), "r"(b[1]));
}

#define LDA 72   // 64 + 8 halves pad
#define LDB 136  // 128 + 8 halves pad

template <bool FUSE>
__global__ __launch_bounds__(256)
void gemm_tc_kernel(const float* __restrict__ W,
                    const float* __restrict__ bias, int M,
                    const int* __restrict__ erow,
                    const int* __restrict__ ecol, int E,
                    int nGemmBlocks) {
    __shared__ __half sA[128 * LDA];
    __shared__ __half sB[2][64 * LDB];    // both K-stages of W
    __shared__ float sBias[128];

    gdc_launch();

    if (FUSE && blockIdx.x >= nGemmBlocks) {
        // ---------------- scatter path (1 edge per thread) ----------------
        gdc_wait();   // g_tmp / rowptr from scanC
        int idx = (blockIdx.x - nGemmBlocks) * blockDim.x + threadIdx.x;
        if (idx < E) {
            int d = __ldg(ecol + idx);
            int s = __ldg(erow + idx);
            int p = atomicAdd(&g_tmp[d], 1);
            g_csr[p] = (unsigned short)s;
        }
        return;
    }

    // ---------------- GEMM path ----------------
    const int t = threadIdx.x;
    const int wid = t >> 5, lane = t & 31;
    const int blockM = blockIdx.x * 128;
    const int warpM = (wid >> 1) * 32;
    const int warpN = (wid & 1) * 64;

    // PDL pre-wait: stage ALL of W + bias (external inputs, dependency-free)
    if (t < 128) sBias[t] = bias[t];
#pragma unroll
    for (int stage = 0; stage < 2; stage++) {
        const int kOff = stage * 64;
#pragma unroll
        for (int l = 0; l < 8; l++) {
            int idx = (t + l * 256) * 4;
            int row = idx >> 7;
            int col = idx & 127;
            float4 v = *(const float4*)(W + (size_t)(kOff + row) * 128 + col);
            __half2 h0 = __floats2half2_rn(v.x, v.y);
            __half2 h1 = __floats2half2_rn(v.z, v.w);
            uint2 pk;
            pk.x = *reinterpret_cast<unsigned*>(&h0);
            pk.y = *reinterpret_cast<unsigned*>(&h1);
            *(uint2*)(sB[stage] + row * LDB + col) = pk;
        }
    }

    float c[2][8][4];
#pragma unroll
    for (int mi = 0; mi < 2; mi++)
#pragma unroll
        for (int ni = 0; ni < 8; ni++)
#pragma unroll
            for (int q = 0; q < 4; q++) c[mi][ni][q] = 0.f;

    gdc_wait();   // g_xh / g_dis producers

#pragma unroll
    for (int stage = 0; stage < 2; stage++) {
        const int kOff = stage * 64;
#pragma unroll
        for (int l = 0; l < 4; l++) {
            int idx = (t + l * 256) * 8;
            int row = idx >> 6;
            int col = idx & 63;
            int grow = blockM + row;
            uint4 v = make_uint4(0u, 0u, 0u, 0u);
            if (grow < M)
                v = *(const uint4*)(g_xh + (size_t)grow * 128 + kOff + col);
            *(uint4*)(sA + row * LDA + col) = v;
        }
        __syncthreads();

#pragma unroll
        for (int ks = 0; ks < 4; ks++) {
            const int kb = ks * 16;
            uint32_t a[2][4];
#pragma unroll
            for (int mi = 0; mi < 2; mi++) {
                int r = warpM + mi * 16 + (lane & 15);
                int cc = kb + ((lane >> 4) << 3);
                ldsm_x4(a[mi], sA + r * LDA + cc);
            }
#pragma unroll
            for (int ni = 0; ni < 8; ni++) {
                uint32_t b[2];
                int r = kb + (lane & 15);
                int cc = warpN + ni * 8;
                ldsm_x2t(b, sB[stage] + r * LDB + cc);
                mma16816(c[0][ni], a[0], b);
                mma16816(c[1][ni], a[1], b);
            }
        }
        __syncthreads();
    }

#pragma unroll
    for (int mi = 0; mi < 2; mi++) {
        int rBase = blockM + warpM + mi * 16 + (lane >> 2);
#pragma unroll
        for (int hh = 0; hh < 2; hh++) {
            int r = rBase + hh * 8;
            if (r < M) {
                float ds = g_dis[r];
#pragma unroll
                for (int ni = 0; ni < 8; ni++) {
                    int col = warpN + ni * 8 + (lane & 3) * 2;
                    float v0 = (c[mi][ni][hh * 2 + 0] + sBias[col]) * ds;
                    float v1 = (c[mi][ni][hh * 2 + 1] + sBias[col + 1]) * ds;
                    __half2 hv = __floats2half2_rn(v0, v1);
                    *(__half2*)(g_hbuf + (size_t)r * 128 + col) = hv;
                }
            }
        }
    }
}

// ======== CSR gather aggregation (fp16 rows, fp32 accumulate) ========
__device__ __forceinline__ void accum_row(float acc[4], const __half* rowp, int lane) {
    uint2 u = *(const uint2*)(rowp + lane * 4);
    __half2 h0 = *reinterpret_cast<__half2*>(&u.x);
    __half2 h1 = *reinterpret_cast<__half2*>(&u.y);
    float2 f0 = __half22float2(h0);
    float2 f1 = __half22float2(h1);
    acc[0] += f0.x; acc[1] += f0.y; acc[2] += f1.x; acc[3] += f1.y;
}

template <bool POOL>
__global__ __launch_bounds__(512)
void aggregate_kernel(int n, const int* __restrict__ batch,
                      const float* __restrict__ Wl) {
    gdc_launch();
    gdc_wait();   // all reads after wait: rowptr/CSR race-free
    int node = blockIdx.x * 16 + (threadIdx.x >> 5);
    if (node >= n) return;
    int lane = threadIdx.x & 31;
    const __half* __restrict__ h = g_hbuf;
    int s = g_rowptr[node];
    int e = g_rowptr[node + 1];
    float acc[4] = {0.f, 0.f, 0.f, 0.f};

    accum_row(acc, h + (size_t)node * 128, lane);   // self loop

    int p = s;
    for (; p + 4 <= e; p += 4) {
        int si[4];
#pragma unroll
        for (int q = 0; q < 4; q++) si[q] = (int)g_csr[p + q];
#pragma unroll
        for (int q = 0; q < 4; q++)
            accum_row(acc, h + (size_t)si[q] * 128, lane);
    }
    for (; p < e; p++)
        accum_row(acc, h + (size_t)(int)g_csr[p] * 128, lane);

    float dd = g_dis[node];
#pragma unroll
    for (int j = 0; j < 4; j++) acc[j] = fmaxf(acc[j] * dd, 0.f);

    if (POOL) {
        float4 w = *(const float4*)(Wl + lane * 4);
        float sv = acc[0] * w.x + acc[1] * w.y + acc[2] * w.z + acc[3] * w.w;
#pragma unroll
        for (int o = 16; o > 0; o >>= 1) sv += __shfl_xor_sync(0xffffffffu, sv, o);
        if (lane == 0) {
            unsigned b = (unsigned)batch[node];
            if (b < NG) {
                atomicAdd(&g_gsum[b], sv);
                atomicAdd(&g_gcnt[b], 1.0f);
            }
        }
    } else {
        __half2 o0 = __floats2half2_rn(acc[0], acc[1]);
        __half2 o1 = __floats2half2_rn(acc[2], acc[3]);
        uint2 pk;
        pk.x = *reinterpret_cast<unsigned*>(&o0);
        pk.y = *reinterpret_cast<unsigned*>(&o1);
        *(uint2*)(g_xh + (size_t)node * 128 + lane * 4) = pk;
        // restore zero-state for next call (runs layers 1,2; idempotent)
        if (lane == 0) g_deg[node] = 0;
    }
}

__global__ void final_kernel(float* __restrict__ out, const float* __restrict__ bl) {
    gdc_wait();
    int g = threadIdx.x;
    if (g < NG) {
        out[g] = g_gsum[g] / fmaxf(g_gcnt[g], 1.0f) + bl[0];
        g_gsum[g] = 0.f;
        g_gcnt[g] = 0.f;
    }
}

// --------------------------------------------------------------------------
template <typename... Args>
static void launch_pdl(void (*kern)(Args...), dim3 grid, dim3 block,
                       Args... args) {
    cudaLaunchConfig_t cfg = {};
    cfg.gridDim = grid;
    cfg.blockDim = block;
    cudaLaunchAttribute attr[1];
    attr[0].id = cudaLaunchAttributeProgrammaticStreamSerialization;
    attr[0].val.programmaticStreamSerializationAllowed = 1;
    cfg.attrs = attr;
    cfg.numAttrs = 1;
    cudaLaunchKernelEx(&cfg, kern, args...);
}

extern "C" void kernel_launch(void* const* d_in, const int* in_sizes, int n_in,
                              void* d_out, int out_size) {
    const float* x     = (const float*)d_in[0];
    const int*   eidx  = (const int*)d_in[1];
    const int*   batch = (const int*)d_in[2];

    int wbase = (in_sizes[3] < 128) ? 4 : 3;
    const float* W1 = (const float*)d_in[wbase + 0];
    const float* b1 = (const float*)d_in[wbase + 1];
    const float* W2 = (const float*)d_in[wbase + 2];
    const float* b2 = (const float*)d_in[wbase + 3];
    const float* W3 = (const float*)d_in[wbase + 4];
    const float* b3 = (const float*)d_in[wbase + 5];
    const float* Wl = (const float*)d_in[wbase + 6];
    const float* bl = (const float*)d_in[wbase + 7];
    float* out = (float*)d_out;

    const int N = in_sizes[0] / F;          // 40000
    const int E = in_sizes[1] / 2;          // 640000
    const int* erow = eidx;
    const int* ecol = eidx + E;
    const int NB = (N + SCAN_TILE - 1) / SCAN_TILE;

    const int T = 256;
    const int total4   = N * F / 4;
    const int cBlocks  = (total4 + T - 1) / T;
    const int eBlocks4 = ((E + 3) / 4 + T - 1) / T;   // prep counting
    const int sBlocks  = (E + T - 1) / T;             // scatter, 1/thread

    const int gemmBlocks = (N + 127) / 128;
    const int aggBlocks  = (N + 15) / 16;

    prep_kernel<<<cBlocks + eBlocks4, T>>>(x, total4, ecol, E, N, cBlocks);

    launch_pdl(scan_phaseA, dim3(NB), dim3(SCAN_TILE), N);
    launch_pdl(scan_phaseC, dim3(NB), dim3(SCAN_TILE), N, NB);

    // layer 1: GEMM fused with edge scatter (independent work, overlapped)
    launch_pdl(gemm_tc_kernel<true>, dim3(gemmBlocks + sBlocks), dim3(256),
               W1, b1, N, erow, ecol, E, gemmBlocks);
    launch_pdl(aggregate_kernel<false>, dim3(aggBlocks), dim3(512), N, batch, Wl);
    // layer 2
    launch_pdl(gemm_tc_kernel<false>, dim3(gemmBlocks), dim3(256),
               W2, b2, N, erow, ecol, E, gemmBlocks);
    launch_pdl(aggregate_kernel<false>, dim3(aggBlocks), dim3(512), N, batch, Wl);
    // layer 3 (+ fused global mean pool)
    launch_pdl(gemm_tc_kernel<false>, dim3(gemmBlocks), dim3(256),
               W3, b3, N, erow, ecol, E, gemmBlocks);
    launch_pdl(aggregate_kernel<true>, dim3(aggBlocks), dim3(512), N, batch, Wl);

    launch_pdl(final_kernel, dim3(1), dim3(64), out, (const float*)bl);
}